// round 1
// baseline (speedup 1.0000x reference)
#include <cuda_runtime.h>
#include <cstddef>

// Problem constants
#define BB   4
#define NN   1024
#define DIMC 1024
#define HH   16
#define DHD  64
__device__ __constant__ float kScale = 0.125f; // 64^-0.5

// Scratch (no cudaMalloc allowed)
__device__ float g_Q[(size_t)BB * NN * DIMC];
__device__ float g_K[(size_t)BB * NN * DIMC];
__device__ float g_V[(size_t)BB * NN * DIMC];
__device__ float g_O[(size_t)BB * NN * DIMC];

// ---------------------------------------------------------------------------
// Generic fp32 GEMM: C[M,Nc] = A[M,K] @ B[K,Nc] (+ bias). 64x64 block tile,
// 256 threads, 4x4 per-thread tile, BK=16.
// ---------------------------------------------------------------------------
__global__ __launch_bounds__(256) void gemm64(
    const float* __restrict__ A, const float* __restrict__ Bm,
    float* __restrict__ C, const float* __restrict__ bias,
    int M, int K, int Nc)
{
    __shared__ float As[16][64];   // As[k][m]
    __shared__ float Bs[16][68];   // Bs[k][n], padded

    const int t  = threadIdx.x;
    const int n0 = blockIdx.x * 64;
    const int m0 = blockIdx.y * 64;
    const int tx = t & 15;         // n direction
    const int ty = t >> 4;         // m direction

    float acc[4][4] = {};

    for (int k0 = 0; k0 < K; k0 += 16) {
        // Load A tile (64 rows x 16 k), store transposed
        {
            int r  = t >> 2;
            int c4 = (t & 3) * 4;
            float4 v = *(const float4*)(A + (size_t)(m0 + r) * K + k0 + c4);
            As[c4 + 0][r] = v.x; As[c4 + 1][r] = v.y;
            As[c4 + 2][r] = v.z; As[c4 + 3][r] = v.w;
        }
        // Load B tile (16 k x 64 n)
        {
            int r  = t >> 4;
            int c4 = (t & 15) * 4;
            float4 v = *(const float4*)(Bm + (size_t)(k0 + r) * Nc + n0 + c4);
            Bs[r][c4 + 0] = v.x; Bs[r][c4 + 1] = v.y;
            Bs[r][c4 + 2] = v.z; Bs[r][c4 + 3] = v.w;
        }
        __syncthreads();
        #pragma unroll
        for (int k = 0; k < 16; k++) {
            float a[4], b[4];
            #pragma unroll
            for (int i = 0; i < 4; i++) a[i] = As[k][ty * 4 + i];
            #pragma unroll
            for (int j = 0; j < 4; j++) b[j] = Bs[k][tx * 4 + j];
            #pragma unroll
            for (int i = 0; i < 4; i++)
                #pragma unroll
                for (int j = 0; j < 4; j++)
                    acc[i][j] += a[i] * b[j];
        }
        __syncthreads();
    }

    #pragma unroll
    for (int i = 0; i < 4; i++) {
        int row = m0 + ty * 4 + i;
        int col = n0 + tx * 4;
        float4 v;
        v.x = acc[i][0]; v.y = acc[i][1]; v.z = acc[i][2]; v.w = acc[i][3];
        if (bias) {
            v.x += bias[col + 0]; v.y += bias[col + 1];
            v.z += bias[col + 2]; v.w += bias[col + 3];
        }
        *(float4*)(C + (size_t)row * Nc + col) = v;
    }
}

// ---------------------------------------------------------------------------
// Fused attention: per (b, h, 16-row tile):
//   scores = (q*scale) @ K^T  -> smem [16][1024]
//   rowwise softmax (max-sub, expf)
//   coalesced float4 store of attn
//   out = p @ V (register accumulators)
// 256 threads. Dynamic smem: sc 16*1024 + qs 16*64 + kv 64*65 floats.
// ---------------------------------------------------------------------------
__global__ __launch_bounds__(256) void attn_fused(
    const float* __restrict__ Q, const float* __restrict__ Kt,
    const float* __restrict__ V, float* __restrict__ attn,
    float* __restrict__ O)
{
    extern __shared__ float sm[];
    float* sc = sm;                  // [16][1024]
    float* qs = sm + 16 * 1024;      // [16][64]
    float* kv = qs + 16 * 64;        // [64][65]
    __shared__ float sinv[16];

    const int t  = threadIdx.x;
    const int i0 = blockIdx.x * 16;
    const int h  = blockIdx.y;
    const int b  = blockIdx.z;
    // element (i, d) of head h lives at base + i*DIMC + d
    const size_t base = (size_t)b * NN * DIMC + (size_t)h * DHD;

    // Load Q tile scaled: 16 rows x 64 cols
    {
        int r  = t >> 4;
        int d4 = (t & 15) * 4;
        float4 v = *(const float4*)(Q + base + (size_t)(i0 + r) * DIMC + d4);
        float* q = qs + r * 64 + d4;
        q[0] = v.x * kScale; q[1] = v.y * kScale;
        q[2] = v.z * kScale; q[3] = v.w * kScale;
    }

    const int tj  = t & 63;   // column within j-tile / d for AV
    const int trb = t >> 6;   // row group base (0..3)

    // ---- scores ----
    for (int jt = 0; jt < 16; jt++) {
        __syncthreads();
        #pragma unroll
        for (int p = 0; p < 4; p++) {
            int l  = p * 256 + t;
            int j  = l >> 4;
            int d4 = (l & 15) * 4;
            float4 v = *(const float4*)(Kt + base + (size_t)(jt * 64 + j) * DIMC + d4);
            float* kd = kv + j * 65 + d4;
            kd[0] = v.x; kd[1] = v.y; kd[2] = v.z; kd[3] = v.w;
        }
        __syncthreads();
        float a0 = 0.f, a1 = 0.f, a2 = 0.f, a3 = 0.f;
        #pragma unroll
        for (int d = 0; d < 64; d++) {
            float kvv = kv[tj * 65 + d];
            a0 += qs[(trb + 0)  * 64 + d] * kvv;
            a1 += qs[(trb + 4)  * 64 + d] * kvv;
            a2 += qs[(trb + 8)  * 64 + d] * kvv;
            a3 += qs[(trb + 12) * 64 + d] * kvv;
        }
        int jc = jt * 64 + tj;
        sc[(trb + 0)  * 1024 + jc] = a0;
        sc[(trb + 4)  * 1024 + jc] = a1;
        sc[(trb + 8)  * 1024 + jc] = a2;
        sc[(trb + 12) * 1024 + jc] = a3;
    }
    __syncthreads();

    // ---- softmax: 16 threads per row ----
    {
        int r = t >> 4, g = t & 15;
        float m = -1e30f;
        for (int j = g; j < 1024; j += 16) m = fmaxf(m, sc[r * 1024 + j]);
        #pragma unroll
        for (int o = 8; o; o >>= 1) m = fmaxf(m, __shfl_xor_sync(0xffffffffu, m, o, 16));
        float s = 0.f;
        for (int j = g; j < 1024; j += 16) {
            float e = __expf(sc[r * 1024 + j] - m);
            sc[r * 1024 + j] = e;
            s += e;
        }
        #pragma unroll
        for (int o = 8; o; o >>= 1) s += __shfl_xor_sync(0xffffffffu, s, o, 16);
        if (g == 0) sinv[r] = 1.f / s;
    }
    __syncthreads();

    // ---- normalize + coalesced attn store ----
    const size_t abase = (((size_t)b * HH + h) * NN + i0) * NN;
    #pragma unroll
    for (int r = 0; r < 16; r++) {
        float inv = sinv[r];
        float4 v = *(float4*)(sc + r * 1024 + t * 4);
        v.x *= inv; v.y *= inv; v.z *= inv; v.w *= inv;
        *(float4*)(sc + r * 1024 + t * 4) = v;
        *(float4*)(attn + abase + (size_t)r * NN + t * 4) = v;
    }

    // ---- AV ----
    float o0 = 0.f, o1 = 0.f, o2 = 0.f, o3 = 0.f;
    for (int jt = 0; jt < 16; jt++) {
        __syncthreads();
        #pragma unroll
        for (int p = 0; p < 4; p++) {
            int l  = p * 256 + t;
            int j  = l >> 4;
            int d4 = (l & 15) * 4;
            float4 v = *(const float4*)(V + base + (size_t)(jt * 64 + j) * DIMC + d4);
            float* kd = kv + j * 65 + d4;
            kd[0] = v.x; kd[1] = v.y; kd[2] = v.z; kd[3] = v.w;
        }
        __syncthreads();
        #pragma unroll
        for (int jj = 0; jj < 64; jj++) {
            float vv  = kv[jj * 65 + tj];
            int jcol  = jt * 64 + jj;
            o0 += sc[(trb + 0)  * 1024 + jcol] * vv;
            o1 += sc[(trb + 4)  * 1024 + jcol] * vv;
            o2 += sc[(trb + 8)  * 1024 + jcol] * vv;
            o3 += sc[(trb + 12) * 1024 + jcol] * vv;
        }
    }
    O[base + (size_t)(i0 + trb + 0)  * DIMC + tj] = o0;
    O[base + (size_t)(i0 + trb + 4)  * DIMC + tj] = o1;
    O[base + (size_t)(i0 + trb + 8)  * DIMC + tj] = o2;
    O[base + (size_t)(i0 + trb + 12) * DIMC + tj] = o3;
}

// ---------------------------------------------------------------------------
extern "C" void kernel_launch(void* const* d_in, const int* in_sizes, int n_in,
                              void* d_out, int out_size)
{
    const float* x  = (const float*)d_in[0];
    const float* Wq = (const float*)d_in[1];
    const float* Wk = (const float*)d_in[2];
    const float* Wv = (const float*)d_in[3];
    const float* Wo = (const float*)d_in[4];
    const float* bo = (const float*)d_in[5];

    float* out  = (float*)d_out;                          // (B, N, DIM)
    float* attn = out + (size_t)BB * NN * DIMC;           // (B, H, N, N)

    float *Qp, *Kp, *Vp, *Op;
    cudaGetSymbolAddress((void**)&Qp, g_Q);
    cudaGetSymbolAddress((void**)&Kp, g_K);
    cudaGetSymbolAddress((void**)&Vp, g_V);
    cudaGetSymbolAddress((void**)&Op, g_O);

    const int M = BB * NN;          // 4096
    const int K = DIMC;             // 1024
    const int Nc = HH * DHD;        // 1024

    dim3 gGemm(Nc / 64, M / 64);    // (16, 64)
    gemm64<<<gGemm, 256>>>(x, Wq, Qp, nullptr, M, K, Nc);
    gemm64<<<gGemm, 256>>>(x, Wk, Kp, nullptr, M, K, Nc);
    gemm64<<<gGemm, 256>>>(x, Wv, Vp, nullptr, M, K, Nc);

    const int smemAttn = (16 * 1024 + 16 * 64 + 64 * 65) * (int)sizeof(float); // 86272
    cudaFuncSetAttribute(attn_fused, cudaFuncAttributeMaxDynamicSharedMemorySize, smemAttn);
    dim3 gAttn(NN / 16, HH, BB);    // (64, 16, 4)
    attn_fused<<<gAttn, 256, smemAttn>>>(Qp, Kp, Vp, attn, Op);

    gemm64<<<gGemm, 256>>>(Op, Wo, out, bo, M, DIMC, DIMC);
}

// round 2
// speedup vs baseline: 1.7028x; 1.7028x over previous
#include <cuda_runtime.h>
#include <cstdint>
#include <cstddef>

#define BB   4
#define NN   1024
#define DIMC 1024
#define HH   16
#define DHD  64

// Scratch (no cudaMalloc allowed)
__device__ float g_Q[(size_t)BB * NN * DIMC];
__device__ float g_K[(size_t)BB * NN * DIMC];
__device__ float g_V[(size_t)BB * NN * DIMC];
__device__ float g_O[(size_t)BB * NN * DIMC];

__device__ __forceinline__ float tf32r(float x) {
    uint32_t u;
    asm("cvt.rna.tf32.f32 %0, %1;" : "=r"(u) : "f"(x));
    return __uint_as_float(u);
}

#define MMA_TF32(d, a0, a1, a2, a3, b0, b1)                                 \
    asm volatile(                                                           \
        "mma.sync.aligned.m16n8k8.row.col.f32.tf32.tf32.f32 "               \
        "{%0,%1,%2,%3}, {%4,%5,%6,%7}, {%8,%9}, {%0,%1,%2,%3};"             \
        : "+f"(d[0]), "+f"(d[1]), "+f"(d[2]), "+f"(d[3])                    \
        : "r"(a0), "r"(a1), "r"(a2), "r"(a3), "r"(b0), "r"(b1))

// ---------------------------------------------------------------------------
// tf32 GEMM: C[M,Nc] = A[M,K] @ B[K,Nc] (+bias).
// 128x128 block, BK=16, 256 threads = 8 warps (2 m x 4 n), warp tile 64x32.
// ---------------------------------------------------------------------------
__global__ __launch_bounds__(256) void gemm_tf32(
    const float* __restrict__ A, const float* __restrict__ Bm,
    float* __restrict__ C, const float* __restrict__ bias,
    int M, int K, int Nc)
{
    __shared__ float As[16][132];   // As[k][m]
    __shared__ float Bs[16][132];   // Bs[k][n]

    const int t     = threadIdx.x;
    const int wid   = t >> 5, lane = t & 31;
    const int group = lane >> 2, tig = lane & 3;
    const int wm    = (wid & 1) * 64;
    const int wn    = (wid >> 1) * 32;
    const int m0    = blockIdx.y * 128;
    const int n0    = blockIdx.x * 128;

    float acc[4][4][4] = {};

    for (int k0 = 0; k0 < K; k0 += 16) {
        #pragma unroll
        for (int l = 0; l < 2; l++) {
            int i = l * 256 + t;
            // A: 128 rows x 16 k -> transposed
            {
                int row = i >> 2, c4 = (i & 3) * 4;
                float4 v = *(const float4*)(A + (size_t)(m0 + row) * K + k0 + c4);
                As[c4 + 0][row] = tf32r(v.x);
                As[c4 + 1][row] = tf32r(v.y);
                As[c4 + 2][row] = tf32r(v.z);
                As[c4 + 3][row] = tf32r(v.w);
            }
            // B: 16 k x 128 n
            {
                int kr = i >> 5, b4 = (i & 31) * 4;
                float4 v = *(const float4*)(Bm + (size_t)(k0 + kr) * Nc + n0 + b4);
                Bs[kr][b4 + 0] = tf32r(v.x);
                Bs[kr][b4 + 1] = tf32r(v.y);
                Bs[kr][b4 + 2] = tf32r(v.z);
                Bs[kr][b4 + 3] = tf32r(v.w);
            }
        }
        __syncthreads();

        #pragma unroll
        for (int ks = 0; ks < 2; ks++) {
            int kk = ks * 8;
            uint32_t a[4][4];
            #pragma unroll
            for (int mf = 0; mf < 4; mf++) {
                int mb = wm + mf * 16;
                a[mf][0] = __float_as_uint(As[kk + tig    ][mb + group    ]);
                a[mf][1] = __float_as_uint(As[kk + tig    ][mb + group + 8]);
                a[mf][2] = __float_as_uint(As[kk + tig + 4][mb + group    ]);
                a[mf][3] = __float_as_uint(As[kk + tig + 4][mb + group + 8]);
            }
            #pragma unroll
            for (int nf = 0; nf < 4; nf++) {
                int nb = wn + nf * 8;
                uint32_t b0 = __float_as_uint(Bs[kk + tig    ][nb + group]);
                uint32_t b1 = __float_as_uint(Bs[kk + tig + 4][nb + group]);
                #pragma unroll
                for (int mf = 0; mf < 4; mf++)
                    MMA_TF32(acc[mf][nf], a[mf][0], a[mf][1], a[mf][2], a[mf][3], b0, b1);
            }
        }
        __syncthreads();
    }

    #pragma unroll
    for (int mf = 0; mf < 4; mf++) {
        #pragma unroll
        for (int nf = 0; nf < 4; nf++) {
            int row = m0 + wm + mf * 16 + group;
            int col = n0 + wn + nf * 8 + tig * 2;
            float bx = bias ? bias[col]     : 0.f;
            float by = bias ? bias[col + 1] : 0.f;
            float2 v0 = make_float2(acc[mf][nf][0] + bx, acc[mf][nf][1] + by);
            float2 v1 = make_float2(acc[mf][nf][2] + bx, acc[mf][nf][3] + by);
            *(float2*)(C + (size_t)row       * Nc + col) = v0;
            *(float2*)(C + (size_t)(row + 8) * Nc + col) = v1;
        }
    }
}

// ---------------------------------------------------------------------------
// Fused attention with tf32 mma. Block = (b, h, 32 q-rows), 256 threads.
// S[32][1028] fp32 scores in smem; QK^T and P@V on tensor cores.
// ---------------------------------------------------------------------------
#define SP 1028
__global__ __launch_bounds__(256) void attn_mma(
    const float* __restrict__ Q, const float* __restrict__ Kt,
    const float* __restrict__ V, float* __restrict__ attn,
    float* __restrict__ O)
{
    extern __shared__ float sm[];
    float* S   = sm;                 // [32][SP]
    float* Qs  = S + 32 * SP;        // [32][68]
    float* KVs = Qs + 32 * 68;       // [64][68]
    __shared__ float sinv[32];

    const int t     = threadIdx.x;
    const int wid   = t >> 5, lane = t & 31;
    const int group = lane >> 2, tig = lane & 3;
    const int wm    = (wid & 1) * 16;   // row sub-tile
    const int wn    = (wid >> 1) * 16;  // col sub-tile
    const int i0    = blockIdx.x * 32;
    const int h     = blockIdx.y, b = blockIdx.z;
    const size_t base = (size_t)b * NN * DIMC + (size_t)h * DHD;

    // Q tile (scaled, tf32)
    #pragma unroll
    for (int l = 0; l < 2; l++) {
        int i = l * 256 + t;
        int r = i >> 4, d4 = (i & 15) * 4;
        float4 v = *(const float4*)(Q + base + (size_t)(i0 + r) * DIMC + d4);
        float* q = Qs + r * 68 + d4;
        q[0] = tf32r(v.x * 0.125f);
        q[1] = tf32r(v.y * 0.125f);
        q[2] = tf32r(v.z * 0.125f);
        q[3] = tf32r(v.w * 0.125f);
    }

    // ---- QK^T ----
    for (int jt = 0; jt < 16; jt++) {
        __syncthreads();
        #pragma unroll
        for (int l = 0; l < 4; l++) {
            int i = l * 256 + t;
            int j = i >> 4, d4 = (i & 15) * 4;
            float4 v = *(const float4*)(Kt + base + (size_t)(jt * 64 + j) * DIMC + d4);
            KVs[(d4 + 0) * 68 + j] = tf32r(v.x);   // transpose: KVs[d][j]
            KVs[(d4 + 1) * 68 + j] = tf32r(v.y);
            KVs[(d4 + 2) * 68 + j] = tf32r(v.z);
            KVs[(d4 + 3) * 68 + j] = tf32r(v.w);
        }
        __syncthreads();

        float acc[2][4] = {};
        #pragma unroll
        for (int ks = 0; ks < 8; ks++) {
            int kk = ks * 8;
            uint32_t a0 = __float_as_uint(Qs[(wm + group    ) * 68 + kk + tig    ]);
            uint32_t a1 = __float_as_uint(Qs[(wm + group + 8) * 68 + kk + tig    ]);
            uint32_t a2 = __float_as_uint(Qs[(wm + group    ) * 68 + kk + tig + 4]);
            uint32_t a3 = __float_as_uint(Qs[(wm + group + 8) * 68 + kk + tig + 4]);
            #pragma unroll
            for (int nf = 0; nf < 2; nf++) {
                int nb = wn + nf * 8;
                uint32_t b0 = __float_as_uint(KVs[(kk + tig    ) * 68 + nb + group]);
                uint32_t b1 = __float_as_uint(KVs[(kk + tig + 4) * 68 + nb + group]);
                MMA_TF32(acc[nf], a0, a1, a2, a3, b0, b1);
            }
        }
        #pragma unroll
        for (int nf = 0; nf < 2; nf++) {
            int col = jt * 64 + wn + nf * 8 + tig * 2;
            int row = wm + group;
            *(float2*)(S + (size_t)row       * SP + col) = make_float2(acc[nf][0], acc[nf][1]);
            *(float2*)(S + (size_t)(row + 8) * SP + col) = make_float2(acc[nf][2], acc[nf][3]);
        }
    }
    __syncthreads();

    // ---- softmax: 8 threads per row ----
    {
        int r = t >> 3, g = t & 7;
        float* row = S + r * SP;
        float m = -1e30f;
        for (int j = g; j < 1024; j += 8) m = fmaxf(m, row[j]);
        #pragma unroll
        for (int o = 4; o; o >>= 1) m = fmaxf(m, __shfl_xor_sync(0xffffffffu, m, o, 8));
        float s = 0.f;
        for (int j = g; j < 1024; j += 8) {
            float e = __expf(row[j] - m);
            row[j] = e;
            s += e;
        }
        #pragma unroll
        for (int o = 4; o; o >>= 1) s += __shfl_xor_sync(0xffffffffu, s, o, 8);
        if (g == 0) sinv[r] = 1.f / s;
    }
    __syncthreads();

    // ---- normalize + coalesced attn store ----
    const size_t abase = (((size_t)b * HH + h) * NN + i0) * NN;
    #pragma unroll
    for (int r = 0; r < 32; r++) {
        float inv = sinv[r];
        float4 v = *(float4*)(S + r * SP + t * 4);
        v.x *= inv; v.y *= inv; v.z *= inv; v.w *= inv;
        *(float4*)(S + r * SP + t * 4) = v;
        *(float4*)(attn + abase + (size_t)r * NN + t * 4) = v;
    }

    // ---- P @ V ----
    float oacc[2][4] = {};
    for (int jt = 0; jt < 16; jt++) {
        __syncthreads();
        #pragma unroll
        for (int l = 0; l < 4; l++) {
            int i = l * 256 + t;
            int j = i >> 4, d4 = (i & 15) * 4;
            float4 v = *(const float4*)(V + base + (size_t)(jt * 64 + j) * DIMC + d4);
            float* kd = KVs + j * 68 + d4;   // KVs[j][d], no transpose
            kd[0] = tf32r(v.x); kd[1] = tf32r(v.y);
            kd[2] = tf32r(v.z); kd[3] = tf32r(v.w);
        }
        __syncthreads();

        #pragma unroll
        for (int ks = 0; ks < 8; ks++) {
            int kk = jt * 64 + ks * 8;
            uint32_t a0 = __float_as_uint(tf32r(S[(wm + group    ) * SP + kk + tig    ]));
            uint32_t a1 = __float_as_uint(tf32r(S[(wm + group + 8) * SP + kk + tig    ]));
            uint32_t a2 = __float_as_uint(tf32r(S[(wm + group    ) * SP + kk + tig + 4]));
            uint32_t a3 = __float_as_uint(tf32r(S[(wm + group + 8) * SP + kk + tig + 4]));
            #pragma unroll
            for (int nf = 0; nf < 2; nf++) {
                int nb = wn + nf * 8;
                uint32_t b0 = __float_as_uint(KVs[(ks * 8 + tig    ) * 68 + nb + group]);
                uint32_t b1 = __float_as_uint(KVs[(ks * 8 + tig + 4) * 68 + nb + group]);
                MMA_TF32(oacc[nf], a0, a1, a2, a3, b0, b1);
            }
        }
    }
    #pragma unroll
    for (int nf = 0; nf < 2; nf++) {
        int d   = wn + nf * 8 + tig * 2;
        int row = i0 + wm + group;
        *(float2*)(O + base + (size_t)row       * DIMC + d) = make_float2(oacc[nf][0], oacc[nf][1]);
        *(float2*)(O + base + (size_t)(row + 8) * DIMC + d) = make_float2(oacc[nf][2], oacc[nf][3]);
    }
}

// ---------------------------------------------------------------------------
extern "C" void kernel_launch(void* const* d_in, const int* in_sizes, int n_in,
                              void* d_out, int out_size)
{
    const float* x  = (const float*)d_in[0];
    const float* Wq = (const float*)d_in[1];
    const float* Wk = (const float*)d_in[2];
    const float* Wv = (const float*)d_in[3];
    const float* Wo = (const float*)d_in[4];
    const float* bo = (const float*)d_in[5];

    float* out  = (float*)d_out;
    float* attn = out + (size_t)BB * NN * DIMC;

    float *Qp, *Kp, *Vp, *Op;
    cudaGetSymbolAddress((void**)&Qp, g_Q);
    cudaGetSymbolAddress((void**)&Kp, g_K);
    cudaGetSymbolAddress((void**)&Vp, g_V);
    cudaGetSymbolAddress((void**)&Op, g_O);

    const int M  = BB * NN;     // 4096
    const int K  = DIMC;        // 1024
    const int Nc = HH * DHD;    // 1024

    dim3 gGemm(Nc / 128, M / 128);   // (8, 32)
    gemm_tf32<<<gGemm, 256>>>(x, Wq, Qp, nullptr, M, K, Nc);
    gemm_tf32<<<gGemm, 256>>>(x, Wk, Kp, nullptr, M, K, Nc);
    gemm_tf32<<<gGemm, 256>>>(x, Wv, Vp, nullptr, M, K, Nc);

    const int smemAttn = (32 * SP + 32 * 68 + 64 * 68) * (int)sizeof(float); // 157696
    cudaFuncSetAttribute(attn_mma, cudaFuncAttributeMaxDynamicSharedMemorySize, smemAttn);
    dim3 gAttn(NN / 32, HH, BB);     // (32, 16, 4)
    attn_mma<<<gAttn, 256, smemAttn>>>(Qp, Kp, Vp, attn, Op);

    gemm_tf32<<<gGemm, 256>>>(Op, Wo, out, bo, M, DIMC, DIMC);
}

// round 3
// speedup vs baseline: 2.7733x; 1.6287x over previous
#include <cuda_runtime.h>
#include <cstdint>
#include <cstddef>

#define BB   4
#define NN   1024
#define DIMC 1024
#define HH   16
#define DHD  64

// Scratch (no cudaMalloc allowed)
__device__ float g_Q[(size_t)BB * NN * DIMC];
__device__ float g_K[(size_t)BB * NN * DIMC];
__device__ float g_V[(size_t)BB * NN * DIMC];
__device__ float g_O[(size_t)BB * NN * DIMC];

__device__ __forceinline__ float tf32r(float x) {
    uint32_t u;
    asm("cvt.rna.tf32.f32 %0, %1;" : "=r"(u) : "f"(x));
    return __uint_as_float(u);
}

#define MMA_TF32(d, a0, a1, a2, a3, b0, b1)                                 \
    asm volatile(                                                           \
        "mma.sync.aligned.m16n8k8.row.col.f32.tf32.tf32.f32 "               \
        "{%0,%1,%2,%3}, {%4,%5,%6,%7}, {%8,%9}, {%0,%1,%2,%3};"             \
        : "+f"(d[0]), "+f"(d[1]), "+f"(d[2]), "+f"(d[3])                    \
        : "r"(a0), "r"(a1), "r"(a2), "r"(a3), "r"(b0), "r"(b1))

// ---------------------------------------------------------------------------
// tf32 GEMM body: C[M,Nc] = A[M,K] @ B[K,Nc] (+bias). 128x128 block, BK=16,
// 256 threads = 8 warps (2m x 4n), warp tile 64x32. Register-prefetch
// double buffering of gmem loads.
// ---------------------------------------------------------------------------
__device__ __forceinline__ void gemm_body(
    const float* __restrict__ A, const float* __restrict__ Bm,
    float* __restrict__ C, const float* __restrict__ bias,
    int M, int K, int Nc)
{
    __shared__ float As[16][132];   // As[k][m]
    __shared__ float Bs[16][132];   // Bs[k][n]

    const int t     = threadIdx.x;
    const int wid   = t >> 5, lane = t & 31;
    const int group = lane >> 2, tig = lane & 3;
    const int wm    = (wid & 1) * 64;
    const int wn    = (wid >> 1) * 32;
    const int m0    = blockIdx.y * 128;
    const int n0    = blockIdx.x * 128;

    float acc[4][4][4] = {};
    float4 pa[2], pb[2];

    auto ldA = [&](int k0, int l) {
        int i = l * 256 + t;
        int row = i >> 2, c4 = (i & 3) * 4;
        return *(const float4*)(A + (size_t)(m0 + row) * K + k0 + c4);
    };
    auto ldB = [&](int k0, int l) {
        int i = l * 256 + t;
        int kr = i >> 5, b4 = (i & 31) * 4;
        return *(const float4*)(Bm + (size_t)(k0 + kr) * Nc + n0 + b4);
    };

    pa[0] = ldA(0, 0); pa[1] = ldA(0, 1);
    pb[0] = ldB(0, 0); pb[1] = ldB(0, 1);

    for (int k0 = 0; k0 < K; k0 += 16) {
        #pragma unroll
        for (int l = 0; l < 2; l++) {
            int i = l * 256 + t;
            int row = i >> 2, c4 = (i & 3) * 4;
            As[c4 + 0][row] = tf32r(pa[l].x);
            As[c4 + 1][row] = tf32r(pa[l].y);
            As[c4 + 2][row] = tf32r(pa[l].z);
            As[c4 + 3][row] = tf32r(pa[l].w);
            int kr = i >> 5, b4 = (i & 31) * 4;
            Bs[kr][b4 + 0] = tf32r(pb[l].x);
            Bs[kr][b4 + 1] = tf32r(pb[l].y);
            Bs[kr][b4 + 2] = tf32r(pb[l].z);
            Bs[kr][b4 + 3] = tf32r(pb[l].w);
        }
        __syncthreads();
        if (k0 + 16 < K) {
            pa[0] = ldA(k0 + 16, 0); pa[1] = ldA(k0 + 16, 1);
            pb[0] = ldB(k0 + 16, 0); pb[1] = ldB(k0 + 16, 1);
        }
        #pragma unroll
        for (int ks = 0; ks < 2; ks++) {
            int kk = ks * 8;
            uint32_t a[4][4];
            #pragma unroll
            for (int mf = 0; mf < 4; mf++) {
                int mb = wm + mf * 16;
                a[mf][0] = __float_as_uint(As[kk + tig    ][mb + group    ]);
                a[mf][1] = __float_as_uint(As[kk + tig    ][mb + group + 8]);
                a[mf][2] = __float_as_uint(As[kk + tig + 4][mb + group    ]);
                a[mf][3] = __float_as_uint(As[kk + tig + 4][mb + group + 8]);
            }
            #pragma unroll
            for (int nf = 0; nf < 4; nf++) {
                int nb = wn + nf * 8;
                uint32_t b0 = __float_as_uint(Bs[kk + tig    ][nb + group]);
                uint32_t b1 = __float_as_uint(Bs[kk + tig + 4][nb + group]);
                #pragma unroll
                for (int mf = 0; mf < 4; mf++)
                    MMA_TF32(acc[mf][nf], a[mf][0], a[mf][1], a[mf][2], a[mf][3], b0, b1);
            }
        }
        __syncthreads();
    }

    #pragma unroll
    for (int mf = 0; mf < 4; mf++) {
        #pragma unroll
        for (int nf = 0; nf < 4; nf++) {
            int row = m0 + wm + mf * 16 + group;
            int col = n0 + wn + nf * 8 + tig * 2;
            float bx = bias ? bias[col]     : 0.f;
            float by = bias ? bias[col + 1] : 0.f;
            *(float2*)(C + (size_t)row       * Nc + col) =
                make_float2(acc[mf][nf][0] + bx, acc[mf][nf][1] + by);
            *(float2*)(C + (size_t)(row + 8) * Nc + col) =
                make_float2(acc[mf][nf][2] + bx, acc[mf][nf][3] + by);
        }
    }
}

__global__ __launch_bounds__(256) void gemm_qkv(
    const float* __restrict__ x,
    const float* __restrict__ Wq, const float* __restrict__ Wk,
    const float* __restrict__ Wv,
    float* __restrict__ Qo, float* __restrict__ Ko, float* __restrict__ Vo)
{
    const float* W = (blockIdx.z == 0) ? Wq : (blockIdx.z == 1) ? Wk : Wv;
    float*       C = (blockIdx.z == 0) ? Qo : (blockIdx.z == 1) ? Ko : Vo;
    gemm_body(x, W, C, nullptr, BB * NN, DIMC, HH * DHD);
}

__global__ __launch_bounds__(256) void gemm_out(
    const float* __restrict__ A, const float* __restrict__ W,
    float* __restrict__ C, const float* __restrict__ bias)
{
    gemm_body(A, W, C, bias, BB * NN, DIMC, DIMC);
}

// ---------------------------------------------------------------------------
// Fused attention. Block = (b, h, 32 q-rows), 512 threads (16 warps).
// QK^T: 128-wide chunks, Q fragments preloaded in registers, K tile in smem
//       (stride 68: conflict-free b-frag LDS), register-prefetch of next chunk.
// softmax: full rows in smem S[32][1028].
// attn store: normalized, coalesced float4.
// P@V: un-normalized S, 2-way k-split across warp halves, V tiles stride 72
//      (conflict-free), smem reduction + sinv scaling in epilogue.
// ---------------------------------------------------------------------------
#define SP  1028
#define KST 68
#define VST 72

__global__ __launch_bounds__(512, 1) void attn_mma(
    const float* __restrict__ Q, const float* __restrict__ Kt,
    const float* __restrict__ V, float* __restrict__ attn,
    float* __restrict__ O)
{
    extern __shared__ float sm[];
    float* S = sm;               // [32][SP]
    float* T = sm + 32 * SP;     // tile region: 2*128*VST floats max
    __shared__ float sinv[32];

    const int t     = threadIdx.x;
    const int wid   = t >> 5, lane = t & 31;
    const int group = lane >> 2, tig = lane & 3;
    const int iq0   = blockIdx.x * 32;
    const int h     = blockIdx.y, b = blockIdx.z;
    const size_t base = (size_t)b * NN * DIMC + (size_t)h * DHD;

    // ---- stage Q (scaled, tf32) into T, read fragments into registers ----
    {
        int r = t >> 4, d4 = (t & 15) * 4;
        float4 v = *(const float4*)(Q + base + (size_t)(iq0 + r) * DIMC + d4);
        float* q = T + r * KST + d4;
        q[0] = tf32r(v.x * 0.125f); q[1] = tf32r(v.y * 0.125f);
        q[2] = tf32r(v.z * 0.125f); q[3] = tf32r(v.w * 0.125f);
    }
    __syncthreads();

    const int wmq = (wid & 1) * 16;   // QK: warp row tile
    const int wnq = (wid >> 1) * 16;  // QK: warp col tile within 128-chunk

    uint32_t qa[8][4];
    #pragma unroll
    for (int ks = 0; ks < 8; ks++) {
        int kk = ks * 8;
        qa[ks][0] = __float_as_uint(T[(wmq + group    ) * KST + kk + tig    ]);
        qa[ks][1] = __float_as_uint(T[(wmq + group + 8) * KST + kk + tig    ]);
        qa[ks][2] = __float_as_uint(T[(wmq + group    ) * KST + kk + tig + 4]);
        qa[ks][3] = __float_as_uint(T[(wmq + group + 8) * KST + kk + tig + 4]);
    }
    __syncthreads();

    // ---- QK^T over 8 chunks of 128 cols ----
    float4 pk[4];
    #pragma unroll
    for (int p = 0; p < 4; p++) {
        int l = p * 512 + t;
        int j = l >> 4, d4 = (l & 15) * 4;
        pk[p] = *(const float4*)(Kt + base + (size_t)j * DIMC + d4);
    }

    for (int c = 0; c < 8; c++) {
        #pragma unroll
        for (int p = 0; p < 4; p++) {
            int l = p * 512 + t;
            int j = l >> 4, d4 = (l & 15) * 4;
            float* kd = T + j * KST + d4;
            kd[0] = tf32r(pk[p].x); kd[1] = tf32r(pk[p].y);
            kd[2] = tf32r(pk[p].z); kd[3] = tf32r(pk[p].w);
        }
        __syncthreads();
        if (c < 7) {
            #pragma unroll
            for (int p = 0; p < 4; p++) {
                int l = p * 512 + t;
                int j = l >> 4, d4 = (l & 15) * 4;
                pk[p] = *(const float4*)(Kt + base + (size_t)((c + 1) * 128 + j) * DIMC + d4);
            }
        }
        float acc[2][4] = {};
        #pragma unroll
        for (int ks = 0; ks < 8; ks++) {
            int kk = ks * 8;
            #pragma unroll
            for (int nf = 0; nf < 2; nf++) {
                int nb = wnq + nf * 8;
                uint32_t b0 = __float_as_uint(T[(nb + group) * KST + kk + tig    ]);
                uint32_t b1 = __float_as_uint(T[(nb + group) * KST + kk + tig + 4]);
                MMA_TF32(acc[nf], qa[ks][0], qa[ks][1], qa[ks][2], qa[ks][3], b0, b1);
            }
        }
        #pragma unroll
        for (int nf = 0; nf < 2; nf++) {
            int col = c * 128 + wnq + nf * 8 + tig * 2;
            *(float2*)(S + (size_t)(wmq + group    ) * SP + col) = make_float2(acc[nf][0], acc[nf][1]);
            *(float2*)(S + (size_t)(wmq + group + 8) * SP + col) = make_float2(acc[nf][2], acc[nf][3]);
        }
        __syncthreads();
    }

    // ---- softmax (exp stored un-normalized; sinv saved) ----
    {
        int r = t >> 4, g = t & 15;
        float* row = S + (size_t)r * SP;
        float m = -1e30f;
        #pragma unroll
        for (int p = 0; p < 16; p++) {
            float4 v = *(const float4*)(row + (p * 16 + g) * 4);
            m = fmaxf(m, fmaxf(fmaxf(v.x, v.y), fmaxf(v.z, v.w)));
        }
        #pragma unroll
        for (int o = 8; o; o >>= 1) m = fmaxf(m, __shfl_xor_sync(0xffffffffu, m, o, 16));
        float s = 0.f;
        #pragma unroll
        for (int p = 0; p < 16; p++) {
            float4 v = *(float4*)(row + (p * 16 + g) * 4);
            v.x = __expf(v.x - m); v.y = __expf(v.y - m);
            v.z = __expf(v.z - m); v.w = __expf(v.w - m);
            s += v.x + v.y + v.z + v.w;
            *(float4*)(row + (p * 16 + g) * 4) = v;
        }
        #pragma unroll
        for (int o = 8; o; o >>= 1) s += __shfl_xor_sync(0xffffffffu, s, o, 16);
        if (g == 0) sinv[r] = 1.f / s;
    }
    __syncthreads();

    // ---- normalized attn store (coalesced) ----
    {
        const size_t abase = (((size_t)b * HH + h) * NN + iq0) * NN;
        #pragma unroll
        for (int p = 0; p < 16; p++) {
            int r  = p * 2 + (t >> 8);
            int c4 = (t & 255) * 4;
            float inv = sinv[r];
            float4 v = *(const float4*)(S + (size_t)r * SP + c4);
            v.x *= inv; v.y *= inv; v.z *= inv; v.w *= inv;
            *(float4*)(attn + abase + (size_t)r * NN + c4) = v;
        }
    }

    // ---- P @ V: 2-way k-split; warp tile m32 n8 ----
    const int nwa = (wid & 7) * 8;
    const int kg  = wid >> 3;
    float oacc[2][4] = {};

    float4 pv[8];
    #pragma unroll
    for (int s = 0; s < 2; s++)
        #pragma unroll
        for (int p = 0; p < 4; p++) {
            int l = p * 512 + t;
            int j = l >> 4, d4 = (l & 15) * 4;
            pv[s * 4 + p] = *(const float4*)(V + base + (size_t)(s * 4 * 128 + j) * DIMC + d4);
        }

    for (int it = 0; it < 4; it++) {
        __syncthreads();   // previous compute done before overwriting T
        #pragma unroll
        for (int s = 0; s < 2; s++)
            #pragma unroll
            for (int p = 0; p < 4; p++) {
                int l = p * 512 + t;
                int j = l >> 4, d4 = (l & 15) * 4;
                float* vd = T + s * 128 * VST + j * VST + d4;
                float4 v = pv[s * 4 + p];
                vd[0] = tf32r(v.x); vd[1] = tf32r(v.y);
                vd[2] = tf32r(v.z); vd[3] = tf32r(v.w);
            }
        __syncthreads();
        if (it < 3) {
            #pragma unroll
            for (int s = 0; s < 2; s++)
                #pragma unroll
                for (int p = 0; p < 4; p++) {
                    int l = p * 512 + t;
                    int j = l >> 4, d4 = (l & 15) * 4;
                    pv[s * 4 + p] = *(const float4*)(
                        V + base + (size_t)((s * 4 + it + 1) * 128 + j) * DIMC + d4);
                }
        }
        const float* Vs = T + kg * 128 * VST;
        const int kcol0 = (kg * 4 + it) * 128;
        #pragma unroll
        for (int ks = 0; ks < 16; ks++) {
            int kk = ks * 8;
            uint32_t b0 = __float_as_uint(Vs[(kk + tig    ) * VST + nwa + group]);
            uint32_t b1 = __float_as_uint(Vs[(kk + tig + 4) * VST + nwa + group]);
            #pragma unroll
            for (int mf = 0; mf < 2; mf++) {
                int mr = mf * 16;
                uint32_t a0 = __float_as_uint(tf32r(S[(size_t)(mr + group    ) * SP + kcol0 + kk + tig    ]));
                uint32_t a1 = __float_as_uint(tf32r(S[(size_t)(mr + group + 8) * SP + kcol0 + kk + tig    ]));
                uint32_t a2 = __float_as_uint(tf32r(S[(size_t)(mr + group    ) * SP + kcol0 + kk + tig + 4]));
                uint32_t a3 = __float_as_uint(tf32r(S[(size_t)(mr + group + 8) * SP + kcol0 + kk + tig + 4]));
                MMA_TF32(oacc[mf], a0, a1, a2, a3, b0, b1);
            }
        }
    }

    // ---- reduce k-split partials, scale by sinv, write O ----
    __syncthreads();
    float* R = T;   // [32][VST]
    if (kg == 1) {
        #pragma unroll
        for (int mf = 0; mf < 2; mf++) {
            int r0 = mf * 16;
            R[(r0 + group    ) * VST + nwa + tig * 2    ] = oacc[mf][0];
            R[(r0 + group    ) * VST + nwa + tig * 2 + 1] = oacc[mf][1];
            R[(r0 + group + 8) * VST + nwa + tig * 2    ] = oacc[mf][2];
            R[(r0 + group + 8) * VST + nwa + tig * 2 + 1] = oacc[mf][3];
        }
    }
    __syncthreads();
    if (kg == 0) {
        #pragma unroll
        for (int mf = 0; mf < 2; mf++) {
            int r0 = mf * 16;
            int ra = r0 + group, rb = r0 + group + 8;
            float ia = sinv[ra], ib = sinv[rb];
            float o0 = (oacc[mf][0] + R[ra * VST + nwa + tig * 2    ]) * ia;
            float o1 = (oacc[mf][1] + R[ra * VST + nwa + tig * 2 + 1]) * ia;
            float o2 = (oacc[mf][2] + R[rb * VST + nwa + tig * 2    ]) * ib;
            float o3 = (oacc[mf][3] + R[rb * VST + nwa + tig * 2 + 1]) * ib;
            *(float2*)(O + base + (size_t)(iq0 + ra) * DIMC + nwa + tig * 2) = make_float2(o0, o1);
            *(float2*)(O + base + (size_t)(iq0 + rb) * DIMC + nwa + tig * 2) = make_float2(o2, o3);
        }
    }
}

// ---------------------------------------------------------------------------
extern "C" void kernel_launch(void* const* d_in, const int* in_sizes, int n_in,
                              void* d_out, int out_size)
{
    const float* x  = (const float*)d_in[0];
    const float* Wq = (const float*)d_in[1];
    const float* Wk = (const float*)d_in[2];
    const float* Wv = (const float*)d_in[3];
    const float* Wo = (const float*)d_in[4];
    const float* bo = (const float*)d_in[5];

    float* out  = (float*)d_out;
    float* attn = out + (size_t)BB * NN * DIMC;

    float *Qp, *Kp, *Vp, *Op;
    cudaGetSymbolAddress((void**)&Qp, g_Q);
    cudaGetSymbolAddress((void**)&Kp, g_K);
    cudaGetSymbolAddress((void**)&Vp, g_V);
    cudaGetSymbolAddress((void**)&Op, g_O);

    dim3 gQKV(8, 32, 3);
    gemm_qkv<<<gQKV, 256>>>(x, Wq, Wk, Wv, Qp, Kp, Vp);

    const int smemAttn = (32 * SP + 2 * 128 * VST) * (int)sizeof(float); // 205312
    cudaFuncSetAttribute(attn_mma, cudaFuncAttributeMaxDynamicSharedMemorySize, smemAttn);
    dim3 gAttn(NN / 32, HH, BB);   // (32, 16, 4)
    attn_mma<<<gAttn, 512, smemAttn>>>(Qp, Kp, Vp, attn, Op);

    dim3 gOut(8, 32);
    gemm_out<<<gOut, 256>>>(Op, Wo, out, bo);
}

// round 4
// speedup vs baseline: 2.9105x; 1.0495x over previous
#include <cuda_runtime.h>
#include <cstdint>
#include <cstddef>

#define BB   4
#define NN   1024
#define DIMC 1024
#define HH   16
#define DHD  64

// Scratch (no cudaMalloc allowed)
__device__ float g_Q[(size_t)BB * NN * DIMC];
__device__ float g_K[(size_t)BB * NN * DIMC];
__device__ float g_V[(size_t)BB * NN * DIMC];
__device__ float g_O[(size_t)BB * NN * DIMC];

__device__ __forceinline__ float tf32r(float x) {
    uint32_t u;
    asm("cvt.rna.tf32.f32 %0, %1;" : "=r"(u) : "f"(x));
    return __uint_as_float(u);
}

#define MMA_TF32(d, a0, a1, a2, a3, b0, b1)                                 \
    asm volatile(                                                           \
        "mma.sync.aligned.m16n8k8.row.col.f32.tf32.tf32.f32 "               \
        "{%0,%1,%2,%3}, {%4,%5,%6,%7}, {%8,%9}, {%0,%1,%2,%3};"             \
        : "+f"(d[0]), "+f"(d[1]), "+f"(d[2]), "+f"(d[3])                    \
        : "r"(a0), "r"(a1), "r"(a2), "r"(a3), "r"(b0), "r"(b1))

// ---------------------------------------------------------------------------
// tf32 GEMM body: C = A[M,K] @ B[K,Nc] (+bias). 128x128 block, BK=16,
// 256 threads = 8 warps (2m x 4n), warp tile 64x32.
// Swizzled smem (stride 136 + XOR col ^ ((k&12)<<1)): conflict-free for
// both the gmem-staging writers and the fragment readers.
// ---------------------------------------------------------------------------
__device__ __forceinline__ void gemm_body(
    const float* __restrict__ A, const float* __restrict__ Bm,
    float* __restrict__ C, const float* __restrict__ bias,
    int M, int K, int Nc)
{
    __shared__ float As[16][136];
    __shared__ float Bs[16][136];

    const int t     = threadIdx.x;
    const int wid   = t >> 5, lane = t & 31;
    const int group = lane >> 2, tig = lane & 3;
    const int wm    = (wid & 1) * 64;
    const int wn    = (wid >> 1) * 32;
    const int m0    = blockIdx.y * 128;
    const int n0    = blockIdx.x * 128;

    float acc[4][4][4] = {};
    float4 pa[2], pb[2];

    auto ldA = [&](int k0, int l) {
        int i = l * 256 + t;
        int row = i >> 2, c4 = (i & 3) * 4;
        return *(const float4*)(A + (size_t)(m0 + row) * K + k0 + c4);
    };
    auto ldB = [&](int k0, int l) {
        int i = l * 256 + t;
        int kr = i >> 5, b4 = (i & 31) * 4;
        return *(const float4*)(Bm + (size_t)(k0 + kr) * Nc + n0 + b4);
    };

    pa[0] = ldA(0, 0); pa[1] = ldA(0, 1);
    pb[0] = ldB(0, 0); pb[1] = ldB(0, 1);

    for (int k0 = 0; k0 < K; k0 += 16) {
        #pragma unroll
        for (int l = 0; l < 2; l++) {
            int i = l * 256 + t;
            int row = i >> 2, c4 = (i & 3) * 4;
            float va[4] = {pa[l].x, pa[l].y, pa[l].z, pa[l].w};
            #pragma unroll
            for (int j = 0; j < 4; j++) {
                int k = c4 + j;
                As[k][row ^ ((k & 12) << 1)] = tf32r(va[j]);
            }
            int kr = i >> 5, b4 = (i & 31) * 4;
            int cb = b4 ^ ((kr & 12) << 1);
            float4 tv;
            tv.x = tf32r(pb[l].x); tv.y = tf32r(pb[l].y);
            tv.z = tf32r(pb[l].z); tv.w = tf32r(pb[l].w);
            *(float4*)&Bs[kr][cb] = tv;
        }
        __syncthreads();
        if (k0 + 16 < K) {
            pa[0] = ldA(k0 + 16, 0); pa[1] = ldA(k0 + 16, 1);
            pb[0] = ldB(k0 + 16, 0); pb[1] = ldB(k0 + 16, 1);
        }
        #pragma unroll
        for (int ks = 0; ks < 2; ks++) {
            int kk = ks * 8;
            int s0 = kk << 1;                 // swizzle for k rows kk..kk+3
            int s1 = ((kk + 4) & 12) << 1;    // swizzle for k rows kk+4..kk+7
            uint32_t a[4][4];
            #pragma unroll
            for (int mf = 0; mf < 4; mf++) {
                int mb = wm + mf * 16;
                a[mf][0] = __float_as_uint(As[kk + tig    ][(mb + group    ) ^ s0]);
                a[mf][1] = __float_as_uint(As[kk + tig    ][(mb + group + 8) ^ s0]);
                a[mf][2] = __float_as_uint(As[kk + tig + 4][(mb + group    ) ^ s1]);
                a[mf][3] = __float_as_uint(As[kk + tig + 4][(mb + group + 8) ^ s1]);
            }
            #pragma unroll
            for (int nf = 0; nf < 4; nf++) {
                int nb = wn + nf * 8;
                uint32_t b0 = __float_as_uint(Bs[kk + tig    ][(nb + group) ^ s0]);
                uint32_t b1 = __float_as_uint(Bs[kk + tig + 4][(nb + group) ^ s1]);
                #pragma unroll
                for (int mf = 0; mf < 4; mf++)
                    MMA_TF32(acc[mf][nf], a[mf][0], a[mf][1], a[mf][2], a[mf][3], b0, b1);
            }
        }
        __syncthreads();
    }

    #pragma unroll
    for (int mf = 0; mf < 4; mf++) {
        #pragma unroll
        for (int nf = 0; nf < 4; nf++) {
            int row = m0 + wm + mf * 16 + group;
            int col = n0 + wn + nf * 8 + tig * 2;
            float bx = bias ? bias[col]     : 0.f;
            float by = bias ? bias[col + 1] : 0.f;
            *(float2*)(C + (size_t)row       * Nc + col) =
                make_float2(acc[mf][nf][0] + bx, acc[mf][nf][1] + by);
            *(float2*)(C + (size_t)(row + 8) * Nc + col) =
                make_float2(acc[mf][nf][2] + bx, acc[mf][nf][3] + by);
        }
    }
}

__global__ __launch_bounds__(256) void gemm_qkv(
    const float* __restrict__ x,
    const float* __restrict__ Wq, const float* __restrict__ Wk,
    const float* __restrict__ Wv,
    float* __restrict__ Qo, float* __restrict__ Ko, float* __restrict__ Vo)
{
    const float* W = (blockIdx.z == 0) ? Wq : (blockIdx.z == 1) ? Wk : Wv;
    float*       C = (blockIdx.z == 0) ? Qo : (blockIdx.z == 1) ? Ko : Vo;
    gemm_body(x, W, C, nullptr, BB * NN, DIMC, HH * DHD);
}

__global__ __launch_bounds__(256) void gemm_out(
    const float* __restrict__ A, const float* __restrict__ W,
    float* __restrict__ C, const float* __restrict__ bias)
{
    gemm_body(A, W, C, bias, BB * NN, DIMC, DIMC);
}

// ---------------------------------------------------------------------------
// attn_qk: per (b, h, 32 q-rows): S = (q*scale)@K^T, softmax, normalized
// attn store. 512 threads. Conflict-free smem strides throughout.
// ---------------------------------------------------------------------------
#define SP  1028
#define KST 68

__global__ __launch_bounds__(512, 1) void attn_qk(
    const float* __restrict__ Q, const float* __restrict__ Kt,
    float* __restrict__ attn)
{
    extern __shared__ float sm[];
    float* S = sm;               // [32][SP]
    float* T = sm + 32 * SP;     // [128][KST]
    __shared__ float sinv[32];

    const int t     = threadIdx.x;
    const int wid   = t >> 5, lane = t & 31;
    const int group = lane >> 2, tig = lane & 3;
    const int iq0   = blockIdx.x * 32;
    const int h     = blockIdx.y, b = blockIdx.z;
    const size_t base = (size_t)b * NN * DIMC + (size_t)h * DHD;

    // stage Q (scaled, tf32), read fragments to registers
    {
        int r = t >> 4, d4 = (t & 15) * 4;
        float4 v = *(const float4*)(Q + base + (size_t)(iq0 + r) * DIMC + d4);
        float* q = T + r * KST + d4;
        q[0] = tf32r(v.x * 0.125f); q[1] = tf32r(v.y * 0.125f);
        q[2] = tf32r(v.z * 0.125f); q[3] = tf32r(v.w * 0.125f);
    }
    __syncthreads();

    const int wmq = (wid & 1) * 16;
    const int wnq = (wid >> 1) * 16;

    uint32_t qa[8][4];
    #pragma unroll
    for (int ks = 0; ks < 8; ks++) {
        int kk = ks * 8;
        qa[ks][0] = __float_as_uint(T[(wmq + group    ) * KST + kk + tig    ]);
        qa[ks][1] = __float_as_uint(T[(wmq + group + 8) * KST + kk + tig    ]);
        qa[ks][2] = __float_as_uint(T[(wmq + group    ) * KST + kk + tig + 4]);
        qa[ks][3] = __float_as_uint(T[(wmq + group + 8) * KST + kk + tig + 4]);
    }
    __syncthreads();

    // QK^T over 8 chunks of 128 cols, register-prefetched
    float4 pk[4];
    #pragma unroll
    for (int p = 0; p < 4; p++) {
        int l = p * 512 + t;
        int j = l >> 4, d4 = (l & 15) * 4;
        pk[p] = *(const float4*)(Kt + base + (size_t)j * DIMC + d4);
    }

    for (int c = 0; c < 8; c++) {
        #pragma unroll
        for (int p = 0; p < 4; p++) {
            int l = p * 512 + t;
            int j = l >> 4, d4 = (l & 15) * 4;
            float* kd = T + j * KST + d4;
            kd[0] = tf32r(pk[p].x); kd[1] = tf32r(pk[p].y);
            kd[2] = tf32r(pk[p].z); kd[3] = tf32r(pk[p].w);
        }
        __syncthreads();
        if (c < 7) {
            #pragma unroll
            for (int p = 0; p < 4; p++) {
                int l = p * 512 + t;
                int j = l >> 4, d4 = (l & 15) * 4;
                pk[p] = *(const float4*)(Kt + base + (size_t)((c + 1) * 128 + j) * DIMC + d4);
            }
        }
        float acc[2][4] = {};
        #pragma unroll
        for (int ks = 0; ks < 8; ks++) {
            int kk = ks * 8;
            #pragma unroll
            for (int nf = 0; nf < 2; nf++) {
                int nb = wnq + nf * 8;
                uint32_t b0 = __float_as_uint(T[(nb + group) * KST + kk + tig    ]);
                uint32_t b1 = __float_as_uint(T[(nb + group) * KST + kk + tig + 4]);
                MMA_TF32(acc[nf], qa[ks][0], qa[ks][1], qa[ks][2], qa[ks][3], b0, b1);
            }
        }
        #pragma unroll
        for (int nf = 0; nf < 2; nf++) {
            int col = c * 128 + wnq + nf * 8 + tig * 2;
            *(float2*)(S + (size_t)(wmq + group    ) * SP + col) = make_float2(acc[nf][0], acc[nf][1]);
            *(float2*)(S + (size_t)(wmq + group + 8) * SP + col) = make_float2(acc[nf][2], acc[nf][3]);
        }
        __syncthreads();
    }

    // softmax
    {
        int r = t >> 4, g = t & 15;
        float* row = S + (size_t)r * SP;
        float m = -1e30f;
        #pragma unroll
        for (int p = 0; p < 16; p++) {
            float4 v = *(const float4*)(row + (p * 16 + g) * 4);
            m = fmaxf(m, fmaxf(fmaxf(v.x, v.y), fmaxf(v.z, v.w)));
        }
        #pragma unroll
        for (int o = 8; o; o >>= 1) m = fmaxf(m, __shfl_xor_sync(0xffffffffu, m, o, 16));
        float s = 0.f;
        #pragma unroll
        for (int p = 0; p < 16; p++) {
            float4 v = *(float4*)(row + (p * 16 + g) * 4);
            v.x = __expf(v.x - m); v.y = __expf(v.y - m);
            v.z = __expf(v.z - m); v.w = __expf(v.w - m);
            s += v.x + v.y + v.z + v.w;
            *(float4*)(row + (p * 16 + g) * 4) = v;
        }
        #pragma unroll
        for (int o = 8; o; o >>= 1) s += __shfl_xor_sync(0xffffffffu, s, o, 16);
        if (g == 0) sinv[r] = 1.f / s;
    }
    __syncthreads();

    // normalized attn store (coalesced float4)
    {
        const size_t abase = (((size_t)b * HH + h) * NN + iq0) * NN;
        #pragma unroll
        for (int p = 0; p < 16; p++) {
            int r  = p * 2 + (t >> 8);
            int c4 = (t & 255) * 4;
            float inv = sinv[r];
            float4 v = *(const float4*)(S + (size_t)r * SP + c4);
            v.x *= inv; v.y *= inv; v.z *= inv; v.w *= inv;
            *(float4*)(attn + abase + (size_t)r * NN + c4) = v;
        }
    }
}

// ---------------------------------------------------------------------------
// pv_gemm: O[b, m, h*64+d] = sum_j attn[b,h,m,j] * V[b, j, h*64+d].
// Block tile 256m x 64n per (mtile, h, b). 256 threads, 8 warps (4m x 2n),
// warp tile 64x32. Swizzled As (stride 264), plain Bs (stride 72).
// ---------------------------------------------------------------------------
__global__ __launch_bounds__(256) void pv_gemm(
    const float* __restrict__ P, const float* __restrict__ V,
    float* __restrict__ O)
{
    __shared__ float As[16][264];
    __shared__ float Bs[16][72];

    const int t     = threadIdx.x;
    const int wid   = t >> 5, lane = t & 31;
    const int group = lane >> 2, tig = lane & 3;
    const int wm    = (wid & 3) * 64;
    const int wn    = (wid >> 2) * 32;
    const int m0    = blockIdx.x * 256;
    const int h     = blockIdx.y, b = blockIdx.z;

    const float* Pb = P + (((size_t)b * HH + h) * NN + m0) * NN;
    const float* Vb = V + (size_t)b * NN * DIMC + (size_t)h * DHD;
    float*       Ob = O + (size_t)b * NN * DIMC + (size_t)h * DHD;

    float acc[4][4][4] = {};
    float4 pa[4], pb;

    auto ldA = [&](int k0, int l) {
        int i = l * 256 + t;
        int row = i >> 2, c4 = (i & 3) * 4;
        return *(const float4*)(Pb + (size_t)row * NN + k0 + c4);
    };
    auto ldB = [&](int k0) {
        int kr = t >> 4, n4 = (t & 15) * 4;
        return *(const float4*)(Vb + (size_t)(k0 + kr) * DIMC + n4);
    };

    #pragma unroll
    for (int l = 0; l < 4; l++) pa[l] = ldA(0, l);
    pb = ldB(0);

    for (int k0 = 0; k0 < NN; k0 += 16) {
        #pragma unroll
        for (int l = 0; l < 4; l++) {
            int i = l * 256 + t;
            int row = i >> 2, c4 = (i & 3) * 4;
            float va[4] = {pa[l].x, pa[l].y, pa[l].z, pa[l].w};
            #pragma unroll
            for (int j = 0; j < 4; j++) {
                int k = c4 + j;
                As[k][row ^ ((k & 12) << 1)] = tf32r(va[j]);
            }
        }
        {
            int kr = t >> 4, n4 = (t & 15) * 4;
            float4 tv;
            tv.x = tf32r(pb.x); tv.y = tf32r(pb.y);
            tv.z = tf32r(pb.z); tv.w = tf32r(pb.w);
            *(float4*)&Bs[kr][n4] = tv;
        }
        __syncthreads();
        if (k0 + 16 < NN) {
            #pragma unroll
            for (int l = 0; l < 4; l++) pa[l] = ldA(k0 + 16, l);
            pb = ldB(k0 + 16);
        }
        #pragma unroll
        for (int ks = 0; ks < 2; ks++) {
            int kk = ks * 8;
            int s0 = kk << 1;
            int s1 = ((kk + 4) & 12) << 1;
            uint32_t a[4][4];
            #pragma unroll
            for (int mf = 0; mf < 4; mf++) {
                int mb = wm + mf * 16;
                a[mf][0] = __float_as_uint(As[kk + tig    ][(mb + group    ) ^ s0]);
                a[mf][1] = __float_as_uint(As[kk + tig    ][(mb + group + 8) ^ s0]);
                a[mf][2] = __float_as_uint(As[kk + tig + 4][(mb + group    ) ^ s1]);
                a[mf][3] = __float_as_uint(As[kk + tig + 4][(mb + group + 8) ^ s1]);
            }
            #pragma unroll
            for (int nf = 0; nf < 4; nf++) {
                int nb = wn + nf * 8;
                uint32_t b0 = __float_as_uint(Bs[kk + tig    ][nb + group]);
                uint32_t b1 = __float_as_uint(Bs[kk + tig + 4][nb + group]);
                #pragma unroll
                for (int mf = 0; mf < 4; mf++)
                    MMA_TF32(acc[mf][nf], a[mf][0], a[mf][1], a[mf][2], a[mf][3], b0, b1);
            }
        }
        __syncthreads();
    }

    #pragma unroll
    for (int mf = 0; mf < 4; mf++) {
        #pragma unroll
        for (int nf = 0; nf < 4; nf++) {
            int row = m0 + wm + mf * 16 + group;
            int col = wn + nf * 8 + tig * 2;
            *(float2*)(Ob + (size_t)row       * DIMC + col) =
                make_float2(acc[mf][nf][0], acc[mf][nf][1]);
            *(float2*)(Ob + (size_t)(row + 8) * DIMC + col) =
                make_float2(acc[mf][nf][2], acc[mf][nf][3]);
        }
    }
}

// ---------------------------------------------------------------------------
extern "C" void kernel_launch(void* const* d_in, const int* in_sizes, int n_in,
                              void* d_out, int out_size)
{
    const float* x  = (const float*)d_in[0];
    const float* Wq = (const float*)d_in[1];
    const float* Wk = (const float*)d_in[2];
    const float* Wv = (const float*)d_in[3];
    const float* Wo = (const float*)d_in[4];
    const float* bo = (const float*)d_in[5];

    float* out  = (float*)d_out;
    float* attn = out + (size_t)BB * NN * DIMC;

    float *Qp, *Kp, *Vp, *Op;
    cudaGetSymbolAddress((void**)&Qp, g_Q);
    cudaGetSymbolAddress((void**)&Kp, g_K);
    cudaGetSymbolAddress((void**)&Vp, g_V);
    cudaGetSymbolAddress((void**)&Op, g_O);

    dim3 gQKV(8, 32, 3);
    gemm_qkv<<<gQKV, 256>>>(x, Wq, Wk, Wv, Qp, Kp, Vp);

    const int smemQK = (32 * SP + 128 * KST) * (int)sizeof(float); // 166400
    cudaFuncSetAttribute(attn_qk, cudaFuncAttributeMaxDynamicSharedMemorySize, smemQK);
    dim3 gQK(NN / 32, HH, BB);
    attn_qk<<<gQK, 512, smemQK>>>(Qp, Kp, attn);

    dim3 gPV(NN / 256, HH, BB);
    pv_gemm<<<gPV, 256>>>(attn, Vp, Op);

    dim3 gOut(8, 32);
    gemm_out<<<gOut, 256>>>(Op, Wo, out, bo);
}